// round 1
// baseline (speedup 1.0000x reference)
#include <cuda_runtime.h>
#include <cuda_bf16.h>

// Problem constants
#define NVEC   65536      // N = B*H*W = 16*64*64
#define KCODE  1024
#define DIM    64
#define HW     4096       // H*W
#define CHW    262144     // C*H*W
#define NB     16

// Output layout (concatenated in reference return order, all fp32)
#define QUANT_OFF 0
#define LOSS_OFF  4194304
#define PERP_OFF  4194305
#define NCS_OFF   4194306
#define EMAW_OFF  4195330
#define EMBW_OFF  4260866

// Scratch (device globals — no allocation allowed)
__device__ int   g_idx[NVEC];
__device__ float g_Wt[DIM * KCODE];   // transposed codebook: Wt[d][k]
__device__ float g_w2[KCODE];
__device__ int   g_counts[KCODE];
__device__ float g_dw[KCODE * DIM];
__device__ float g_loss;

// ---------------------------------------------------------------------------
// Kernel A: prep — transpose W, compute ||w||^2, zero accumulators
// grid 256 x 256 threads = 65536
// ---------------------------------------------------------------------------
__global__ void prep_kernel(const float* __restrict__ W) {
    int i = blockIdx.x * 256 + threadIdx.x;   // 0..65535
    g_dw[i] = 0.f;
    int d = i >> 10;
    int k = i & 1023;
    g_Wt[i] = W[k * DIM + d];
    if (i < KCODE) {
        g_counts[i] = 0;
        const float* row = W + i * DIM;
        float s = 0.f;
        #pragma unroll
        for (int dd = 0; dd < DIM; ++dd) {
            float v = row[dd];
            s = fmaf(v, v, s);
        }
        g_w2[i] = s;
    }
    if (i == 0) g_loss = 0.f;
}

// ---------------------------------------------------------------------------
// Kernel B: fused distance-GEMM + argmin + counts + dw scatter.
// Block: 256 threads (tx = tid%16 codes, ty = tid/16 rows).
// Block tile: 128 rows x 64 codes per iteration, loop 16 code tiles.
// Thread tile: 8 rows x 4 codes (fp32 FMA).
// ---------------------------------------------------------------------------
__global__ void __launch_bounds__(256) argmin_kernel(const float* __restrict__ in) {
    __shared__ float xs[DIM][128];                // 32 KB, xs[d][row]
    __shared__ union USm {
        float ws[DIM][64];                        // 16 KB, ws[d][k]
        struct { float rv[128][16]; int ri[128][16]; } red;
    } u;

    const int tid = threadIdx.x;
    const int tx  = tid & 15;
    const int ty  = tid >> 4;
    const int n0  = blockIdx.x * 128;
    const int b   = n0 >> 12;          // 4096 rows per image
    const int hw0 = n0 & 4095;

    // --- load x tile: xs[d][c] = in[b*CHW + d*HW + hw0 + c], fully coalesced
    const float* src = in + (size_t)b * CHW + hw0;
    #pragma unroll
    for (int i = 0; i < 8; ++i) {
        int fidx = i * 256 + tid;          // float4 index over 64x32
        int d  = fidx >> 5;
        int c4 = fidx & 31;
        float4 v = __ldg(reinterpret_cast<const float4*>(src + d * HW + c4 * 4));
        *reinterpret_cast<float4*>(&xs[d][c4 * 4]) = v;
    }

    float minv[8];
    int   mink[8];
    #pragma unroll
    for (int r = 0; r < 8; ++r) { minv[r] = 3.4e38f; mink[r] = 0; }

    __syncthreads();

    for (int tile = 0; tile < 16; ++tile) {
        // load code tile: ws[d][kk] from g_Wt (already [d][k] layout → coalesced)
        #pragma unroll
        for (int i = 0; i < 4; ++i) {
            int fidx = i * 256 + tid;      // float4 index over 64x16
            int d  = fidx >> 4;
            int c4 = fidx & 15;
            float4 v = __ldg(reinterpret_cast<const float4*>(
                             &g_Wt[d * KCODE + tile * 64 + c4 * 4]));
            *reinterpret_cast<float4*>(&u.ws[d][c4 * 4]) = v;
        }
        __syncthreads();

        float acc[8][4];
        #pragma unroll
        for (int r = 0; r < 8; ++r)
            #pragma unroll
            for (int j = 0; j < 4; ++j) acc[r][j] = 0.f;

        #pragma unroll 4
        for (int d = 0; d < DIM; ++d) {
            float4 a0 = *reinterpret_cast<const float4*>(&xs[d][ty * 4]);
            float4 a1 = *reinterpret_cast<const float4*>(&xs[d][64 + ty * 4]);
            float4 bb = *reinterpret_cast<const float4*>(&u.ws[d][tx * 4]);
            float ar[8] = {a0.x, a0.y, a0.z, a0.w, a1.x, a1.y, a1.z, a1.w};
            float br[4] = {bb.x, bb.y, bb.z, bb.w};
            #pragma unroll
            for (int r = 0; r < 8; ++r)
                #pragma unroll
                for (int j = 0; j < 4; ++j)
                    acc[r][j] = fmaf(ar[r], br[j], acc[r][j]);
        }

        // epilogue: dist = w2 - 2*dot (x^2 constant per row, argmin-invariant)
        #pragma unroll
        for (int j = 0; j < 4; ++j) {
            int kg = tile * 64 + tx * 4 + j;
            float w2v = __ldg(&g_w2[kg]);
            #pragma unroll
            for (int r = 0; r < 8; ++r) {
                float v = fmaf(-2.f, acc[r][j], w2v);
                if (v < minv[r]) { minv[r] = v; mink[r] = kg; }
            }
        }
        __syncthreads();   // before overwriting ws next tile / red at end
    }

    // --- cross-thread reduction (16 candidates per row)
    #pragma unroll
    for (int r = 0; r < 8; ++r) {
        int row = (r < 4) ? (ty * 4 + r) : (64 + ty * 4 + (r - 4));
        u.red.rv[row][tx] = minv[r];
        u.red.ri[row][tx] = mink[r];
    }
    __syncthreads();

    if (tid < 128) {
        float bv = u.red.rv[tid][0];
        int   bi = u.red.ri[tid][0];
        #pragma unroll
        for (int t = 1; t < 16; ++t) {
            float v = u.red.rv[tid][t];
            int   ii = u.red.ri[tid][t];
            if (v < bv || (v == bv && ii < bi)) { bv = v; bi = ii; }
        }
        g_idx[n0 + tid] = bi;
        atomicAdd(&g_counts[bi], 1);
        u.red.ri[tid][0] = bi;     // publish for dw scatter
    }
    __syncthreads();

    // --- dw scatter: dw[k][d] += x[n][d] (x is in smem)
    int row   = tid >> 1;
    int dbase = (tid & 1) * 32;
    int kk = u.red.ri[row][0];
    float* dst = &g_dw[kk * DIM + dbase];
    #pragma unroll
    for (int i = 0; i < 32; ++i)
        atomicAdd(&dst[i], xs[dbase + i][row]);
}

// ---------------------------------------------------------------------------
// Kernel C: codebook EMA update + perplexity (single block, 1024 threads)
// ---------------------------------------------------------------------------
__global__ void update_kernel(const float* __restrict__ ecs,
                              const float* __restrict__ emw,
                              float* __restrict__ out) {
    int k = threadIdx.x;
    __shared__ float sm[KCODE];

    float c   = (float)g_counts[k];
    float ncs = ecs[k] * 0.99f + 0.01f * c;
    out[NCS_OFF + k] = ncs;

    sm[k] = ncs; __syncthreads();
    for (int s = 512; s > 0; s >>= 1) {
        if (k < s) sm[k] += sm[k + s];
        __syncthreads();
    }
    float nsum = sm[0];
    __syncthreads();

    // perplexity
    float p = c * (1.f / (float)NVEC);
    sm[k] = p * logf(p + 1e-10f);
    __syncthreads();
    for (int s = 512; s > 0; s >>= 1) {
        if (k < s) sm[k] += sm[k + s];
        __syncthreads();
    }
    if (k == 0) out[PERP_OFF] = expf(-sm[0]);

    float normalized = (ncs + 1e-5f) / (nsum + 1024.f * 1e-5f) * nsum;
    #pragma unroll
    for (int d = 0; d < DIM; ++d) {
        int i = k * DIM + d;
        float nw = emw[i] * 0.99f + 0.01f * g_dw[i];
        out[EMAW_OFF + i] = nw;
        out[EMBW_OFF + i] = nw / normalized;
    }
}

// ---------------------------------------------------------------------------
// Kernel D: quantize (gather updated codebook) + loss partial sums
// grid = 16*64 blocks (one per (b,d) plane), 256 threads, 16 elems/thread.
// Reads/writes in [B, D, H, W] layout → coalesced; codebook gather hits L2.
// ---------------------------------------------------------------------------
__global__ void quant_kernel(const float* __restrict__ in,
                             float* __restrict__ out) {
    int blk = blockIdx.x;
    int b = blk >> 6;
    int d = blk & 63;
    const float* __restrict__ E = out + EMBW_OFF;
    int base  = b * CHW + d * HW;
    int nbase = b * HW;
    int t = threadIdx.x;

    float local = 0.f;
    #pragma unroll
    for (int it = 0; it < 16; ++it) {
        int hw = t + it * 256;
        int kk = g_idx[nbase + hw];
        float q = __ldg(&E[kk * DIM + d]);
        float x = in[base + hw];
        out[QUANT_OFF + base + hw] = q;   // x + (q - x) == q up to 1 ulp
        float diff = x - q;
        local = fmaf(diff, diff, local);
    }

    #pragma unroll
    for (int o = 16; o > 0; o >>= 1)
        local += __shfl_down_sync(0xffffffff, local, o);
    __shared__ float wsum[8];
    if ((t & 31) == 0) wsum[t >> 5] = local;
    __syncthreads();
    if (t == 0) {
        float s = 0.f;
        #pragma unroll
        for (int i = 0; i < 8; ++i) s += wsum[i];
        atomicAdd(&g_loss, s);
    }
}

// ---------------------------------------------------------------------------
// Kernel E: finalize loss
// ---------------------------------------------------------------------------
__global__ void loss_kernel(float* __restrict__ out) {
    out[LOSS_OFF] = 0.25f * g_loss * (1.f / (float)(NVEC * DIM));
}

extern "C" void kernel_launch(void* const* d_in, const int* in_sizes, int n_in,
                              void* d_out, int out_size) {
    const float* in  = (const float*)d_in[0];  // [16,64,64,64]
    const float* W   = (const float*)d_in[1];  // [1024,64]
    const float* ecs = (const float*)d_in[2];  // [1024]
    const float* emw = (const float*)d_in[3];  // [1024,64]
    float* out = (float*)d_out;

    prep_kernel<<<256, 256>>>(W);
    argmin_kernel<<<NVEC / 128, 256>>>(in);
    update_kernel<<<1, 1024>>>(ecs, emw, out);
    quant_kernel<<<NB * DIM, 256>>>(in, out);
    loss_kernel<<<1, 1>>>(out);
}

// round 2
// speedup vs baseline: 1.0337x; 1.0337x over previous
#include <cuda_runtime.h>
#include <cuda_bf16.h>

// Problem constants
#define NVEC   65536      // N = B*H*W = 16*64*64
#define KCODE  1024
#define DIM    64
#define HW     4096       // H*W
#define CHW    262144     // C*H*W
#define NB     16

// Output layout (concatenated in reference return order, all fp32)
#define QUANT_OFF 0
#define LOSS_OFF  4194304
#define PERP_OFF  4194305
#define NCS_OFF   4194306
#define EMAW_OFF  4195330
#define EMBW_OFF  4260866

#define NTILES   1024     // 64-row tiles
#define GRID_ARG 592      // 148 SMs * 4

// Scratch (device globals — no allocation allowed)
__device__ int   g_idx[NVEC];
__device__ __align__(16) float g_Wt[DIM * KCODE];     // Wt[d][k]
__device__ float g_w2[KCODE];
__device__ int   g_counts[KCODE];
__device__ __align__(16) float g_dw[KCODE * DIM];
__device__ __align__(16) float g_embed[KCODE * DIM];  // aligned copy of new codebook
__device__ float g_loss;
__device__ int   g_tile;

// ---------------------------------------------------------------------------
// Kernel A: prep — transpose W, ||w||^2, zero accumulators, reset tile counter
// ---------------------------------------------------------------------------
__global__ void prep_kernel(const float* __restrict__ W) {
    int i = blockIdx.x * 256 + threadIdx.x;   // 0..65535
    g_dw[i] = 0.f;
    int d = i >> 10;
    int k = i & 1023;
    g_Wt[i] = W[k * DIM + d];
    if (i < KCODE) {
        g_counts[i] = 0;
        const float* row = W + i * DIM;
        float s = 0.f;
        #pragma unroll
        for (int dd = 0; dd < DIM; ++dd) {
            float v = row[dd];
            s = fmaf(v, v, s);
        }
        g_w2[i] = s;
    }
    if (i == 0) { g_loss = 0.f; g_tile = 0; }
}

// ---------------------------------------------------------------------------
// Kernel B: persistent fused distance-GEMM + argmin + counts + dw scatter.
// Work unit: 64-row tile, pulled from a global atomic counter (1024 tiles).
// Per tile: loop 16 code-tiles of 64. Thread tile: 4 rows x 4 codes.
// ---------------------------------------------------------------------------
__global__ void __launch_bounds__(256) argmin_kernel(const float* __restrict__ in) {
    __shared__ __align__(16) float xs[DIM][64];      // 16 KB, xs[d][row]
    __shared__ union USm {
        float ws[DIM][64];                           // 16 KB, ws[d][k]
        struct { float rv[64][16]; int ri[64][16]; } red;   // 8 KB
    } u;
    __shared__ int s_tile;

    const int tid = threadIdx.x;
    const int tx  = tid & 15;        // code group
    const int ty  = tid >> 4;        // row group

    for (;;) {
        if (tid == 0) s_tile = atomicAdd(&g_tile, 1);
        __syncthreads();
        const int tile = s_tile;
        if (tile >= NTILES) return;

        const int n0  = tile * 64;
        const int b   = n0 >> 12;        // 4096 rows per image
        const int hw0 = n0 & 4095;

        // --- load x tile: xs[d][c] = in[b*CHW + d*HW + hw0 + c], coalesced
        const float* src = in + (size_t)b * CHW + hw0;
        #pragma unroll
        for (int i = 0; i < 4; ++i) {
            int fidx = i * 256 + tid;          // float4 index over 64x16
            int d  = fidx >> 4;
            int c4 = fidx & 15;
            float4 v = __ldg(reinterpret_cast<const float4*>(src + d * HW + c4 * 4));
            *reinterpret_cast<float4*>(&xs[d][c4 * 4]) = v;
        }

        float minv[4];
        int   mink[4];
        #pragma unroll
        for (int r = 0; r < 4; ++r) { minv[r] = 3.4e38f; mink[r] = 0; }

        __syncthreads();

        for (int t16 = 0; t16 < 16; ++t16) {
            // load code tile (g_Wt is [d][k] → coalesced)
            #pragma unroll
            for (int i = 0; i < 4; ++i) {
                int fidx = i * 256 + tid;      // float4 index over 64x16
                int d  = fidx >> 4;
                int c4 = fidx & 15;
                float4 v = __ldg(reinterpret_cast<const float4*>(
                                 &g_Wt[d * KCODE + t16 * 64 + c4 * 4]));
                *reinterpret_cast<float4*>(&u.ws[d][c4 * 4]) = v;
            }
            __syncthreads();

            float acc[4][4];
            #pragma unroll
            for (int r = 0; r < 4; ++r)
                #pragma unroll
                for (int j = 0; j < 4; ++j) acc[r][j] = 0.f;

            #pragma unroll 8
            for (int d = 0; d < DIM; ++d) {
                float4 a  = *reinterpret_cast<const float4*>(&xs[d][ty * 4]);
                float4 bb = *reinterpret_cast<const float4*>(&u.ws[d][tx * 4]);
                float ar[4] = {a.x, a.y, a.z, a.w};
                float br[4] = {bb.x, bb.y, bb.z, bb.w};
                #pragma unroll
                for (int r = 0; r < 4; ++r)
                    #pragma unroll
                    for (int j = 0; j < 4; ++j)
                        acc[r][j] = fmaf(ar[r], br[j], acc[r][j]);
            }

            // epilogue: dist = w2 - 2*dot (x^2 per-row constant, argmin-invariant)
            #pragma unroll
            for (int j = 0; j < 4; ++j) {
                int kg = t16 * 64 + tx * 4 + j;
                float w2v = __ldg(&g_w2[kg]);
                #pragma unroll
                for (int r = 0; r < 4; ++r) {
                    float v = fmaf(-2.f, acc[r][j], w2v);
                    if (v < minv[r]) { minv[r] = v; mink[r] = kg; }
                }
            }
            __syncthreads();   // before overwriting ws / red
        }

        // --- cross-thread reduction (16 candidates per row)
        #pragma unroll
        for (int r = 0; r < 4; ++r) {
            int row = ty * 4 + r;
            u.red.rv[row][tx] = minv[r];
            u.red.ri[row][tx] = mink[r];
        }
        __syncthreads();

        if (tid < 64) {
            float bv = u.red.rv[tid][0];
            int   bi = u.red.ri[tid][0];
            #pragma unroll
            for (int t = 1; t < 16; ++t) {
                float v  = u.red.rv[tid][t];
                int   ii = u.red.ri[tid][t];
                if (v < bv || (v == bv && ii < bi)) { bv = v; bi = ii; }
            }
            g_idx[n0 + tid] = bi;
            atomicAdd(&g_counts[bi], 1);
            u.red.ri[tid][0] = bi;     // publish for dw scatter
        }
        __syncthreads();

        // --- dw scatter: dw[k][d] += x[n][d] (conflict-free: 32 distinct rows/warp)
        {
            int row   = tid & 63;
            int dbase = (tid >> 6) * 16;
            int kk = u.red.ri[row][0];
            float* dst = &g_dw[kk * DIM + dbase];
            #pragma unroll
            for (int i = 0; i < 16; ++i)
                atomicAdd(&dst[i], xs[dbase + i][row]);
        }
        __syncthreads();   // protect xs / red before next tile
    }
}

// ---------------------------------------------------------------------------
// Kernel C: codebook EMA update + perplexity (single block, 1024 threads)
// ---------------------------------------------------------------------------
__global__ void update_kernel(const float* __restrict__ ecs,
                              const float* __restrict__ emw,
                              float* __restrict__ out) {
    int k = threadIdx.x;
    __shared__ float sm[KCODE];

    float c   = (float)g_counts[k];
    float ncs = ecs[k] * 0.99f + 0.01f * c;
    out[NCS_OFF + k] = ncs;

    sm[k] = ncs; __syncthreads();
    for (int s = 512; s > 0; s >>= 1) {
        if (k < s) sm[k] += sm[k + s];
        __syncthreads();
    }
    float nsum = sm[0];
    __syncthreads();

    // perplexity
    float p = c * (1.f / (float)NVEC);
    sm[k] = p * logf(p + 1e-10f);
    __syncthreads();
    for (int s = 512; s > 0; s >>= 1) {
        if (k < s) sm[k] += sm[k + s];
        __syncthreads();
    }
    if (k == 0) out[PERP_OFF] = expf(-sm[0]);

    float normalized = (ncs + 1e-5f) / (nsum + 1024.f * 1e-5f) * nsum;
    float inv = 1.f / normalized;
    #pragma unroll
    for (int d = 0; d < DIM; ++d) {
        int i = k * DIM + d;
        float nw = emw[i] * 0.99f + 0.01f * g_dw[i];
        float e  = nw * inv;
        out[EMAW_OFF + i] = nw;
        out[EMBW_OFF + i] = e;
        g_embed[i] = e;            // aligned copy for float4 gathers in quant
    }
}

// ---------------------------------------------------------------------------
// Kernel D: quantize + loss. Each thread covers 4 consecutive d's per row so
// the codebook gather is one aligned float4 (from g_embed). grid = 1024.
//   blk: b = blk>>6, dgroup = (blk>>2)&15, hwchunk = blk&3
// ---------------------------------------------------------------------------
__global__ void quant_kernel(const float* __restrict__ in,
                             float* __restrict__ out) {
    int blk = blockIdx.x;
    int b  = blk >> 6;
    int d0 = ((blk >> 2) & 15) * 4;
    int hc = blk & 3;
    int t  = threadIdx.x;

    const size_t pbase = (size_t)b * CHW + (size_t)d0 * HW;
    const int nbase = b * HW;

    float local = 0.f;
    #pragma unroll
    for (int it = 0; it < 4; ++it) {
        int hw = hc * 1024 + it * 256 + t;
        int kk = g_idx[nbase + hw];
        float4 q = *reinterpret_cast<const float4*>(&g_embed[kk * DIM + d0]);
        float qa[4] = {q.x, q.y, q.z, q.w};
        #pragma unroll
        for (int j = 0; j < 4; ++j) {
            size_t off = pbase + (size_t)j * HW + hw;
            float x = in[off];
            out[QUANT_OFF + off] = qa[j];   // x + (q - x) == q
            float diff = x - qa[j];
            local = fmaf(diff, diff, local);
        }
    }

    #pragma unroll
    for (int o = 16; o > 0; o >>= 1)
        local += __shfl_down_sync(0xffffffff, local, o);
    __shared__ float wsum[8];
    if ((t & 31) == 0) wsum[t >> 5] = local;
    __syncthreads();
    if (t == 0) {
        float s = 0.f;
        #pragma unroll
        for (int i = 0; i < 8; ++i) s += wsum[i];
        atomicAdd(&g_loss, s);
    }
}

// ---------------------------------------------------------------------------
// Kernel E: finalize loss
// ---------------------------------------------------------------------------
__global__ void loss_kernel(float* __restrict__ out) {
    out[LOSS_OFF] = 0.25f * g_loss * (1.f / (float)(NVEC * DIM));
}

extern "C" void kernel_launch(void* const* d_in, const int* in_sizes, int n_in,
                              void* d_out, int out_size) {
    const float* in  = (const float*)d_in[0];  // [16,64,64,64]
    const float* W   = (const float*)d_in[1];  // [1024,64]
    const float* ecs = (const float*)d_in[2];  // [1024]
    const float* emw = (const float*)d_in[3];  // [1024,64]
    float* out = (float*)d_out;

    prep_kernel<<<256, 256>>>(W);
    argmin_kernel<<<GRID_ARG, 256>>>(in);
    update_kernel<<<1, 1024>>>(ecs, emw, out);
    quant_kernel<<<1024, 256>>>(in, out);
    loss_kernel<<<1, 1>>>(out);
}

// round 5
// speedup vs baseline: 1.1791x; 1.1407x over previous
#include <cuda_runtime.h>
#include <cuda_bf16.h>

// Problem constants
#define NVEC   65536      // N = B*H*W = 16*64*64
#define KCODE  1024
#define DIM    64
#define HW     4096       // H*W
#define CHW    262144     // C*H*W
#define NB     16

// Output layout (concatenated in reference return order, all fp32)
#define QUANT_OFF 0
#define LOSS_OFF  4194304
#define PERP_OFF  4194305
#define NCS_OFF   4194306
#define EMAW_OFF  4195330
#define EMBW_OFF  4260866

#define NTILES   1024     // 64-row tiles
#define GRID_ARG 592      // 148 SMs * 4 blocks

// Scratch (device globals — no allocation allowed)
__device__ int   g_idx[NVEC];
__device__ __align__(16) float g_Wt[DIM * KCODE];     // Wt[d][k]
__device__ float g_w2[KCODE];
__device__ int   g_counts[KCODE];
__device__ __align__(16) float g_dw[KCODE * DIM];
__device__ __align__(16) float g_embed[KCODE * DIM];  // aligned copy of new codebook
__device__ float g_loss;
__device__ int   g_tile;

// ---------------------------------------------------------------------------
// Kernel A: prep — transpose W, ||w||^2, zero accumulators, reset tile counter
// ---------------------------------------------------------------------------
__global__ void prep_kernel(const float* __restrict__ W) {
    int i = blockIdx.x * 256 + threadIdx.x;   // 0..65535
    g_dw[i] = 0.f;
    int d = i >> 10;
    int k = i & 1023;
    g_Wt[i] = W[k * DIM + d];
    if (i < KCODE) {
        g_counts[i] = 0;
        const float* row = W + i * DIM;
        float s = 0.f;
        #pragma unroll
        for (int dd = 0; dd < DIM; ++dd) {
            float v = row[dd];
            s = fmaf(v, v, s);
        }
        g_w2[i] = s;
    }
    if (i == 0) { g_loss = 0.f; g_tile = 0; }
}

// ---------------------------------------------------------------------------
// Kernel B: persistent fused distance-GEMM + argmin + counts + dw scatter.
// 128 threads. Block tile: 64 rows x 128 codes (8 code-tiles of 128).
// Thread tile: 8 rows x 8 codes -> 64 B LDS per 64 MACs (1 B/MAC, FMA-bound).
// Smem: exactly 48 KB (xs 16K + ws/red union 32K); tile index is bounced
// through xs[0][0] to stay under the 0xc000 static-smem cap.
// ---------------------------------------------------------------------------
__global__ void __launch_bounds__(128) argmin_kernel(const float* __restrict__ in) {
    __shared__ __align__(16) float xs[DIM][64];      // 16 KB, xs[d][row]
    __shared__ union USm {
        float ws[DIM][128];                          // 32 KB, ws[d][k]
        struct { float rv[64][16]; int ri[64][16]; } red;   // 8 KB overlay
    } u;

    const int tid = threadIdx.x;     // 0..127
    const int tx  = tid & 15;        // code group (16 x 8 codes)
    const int ty  = tid >> 4;        // row group  (8 x 8 rows)

    for (;;) {
        if (tid == 0)
            *reinterpret_cast<volatile int*>(&xs[0][0]) = atomicAdd(&g_tile, 1);
        __syncthreads();
        const int tile = *reinterpret_cast<volatile int*>(&xs[0][0]);
        __syncthreads();              // all threads read tile before xs overwrite
        if (tile >= NTILES) return;

        const int n0  = tile * 64;
        const int b   = n0 >> 12;        // 4096 rows per image
        const int hw0 = n0 & 4095;

        // --- load x tile: xs[d][c] = in[b*CHW + d*HW + hw0 + c], coalesced
        const float* src = in + (size_t)b * CHW + hw0;
        #pragma unroll
        for (int i = 0; i < 8; ++i) {
            int fidx = i * 128 + tid;          // float4 index over 64x16
            int d  = fidx >> 4;
            int c4 = fidx & 15;
            float4 v = __ldg(reinterpret_cast<const float4*>(src + d * HW + c4 * 4));
            *reinterpret_cast<float4*>(&xs[d][c4 * 4]) = v;
        }

        float minv[8];
        int   mink[8];
        #pragma unroll
        for (int r = 0; r < 8; ++r) { minv[r] = 3.4e38f; mink[r] = 0; }

        __syncthreads();

        for (int t8 = 0; t8 < 8; ++t8) {
            // load 64x128 code tile (g_Wt is [d][k] -> coalesced)
            #pragma unroll
            for (int i = 0; i < 16; ++i) {
                int fidx = i * 128 + tid;      // float4 index over 64x32
                int d  = fidx >> 5;
                int c4 = fidx & 31;
                float4 v = __ldg(reinterpret_cast<const float4*>(
                                 &g_Wt[d * KCODE + t8 * 128 + c4 * 4]));
                *reinterpret_cast<float4*>(&u.ws[d][c4 * 4]) = v;
            }
            __syncthreads();

            float acc[8][8];
            #pragma unroll
            for (int r = 0; r < 8; ++r)
                #pragma unroll
                for (int j = 0; j < 8; ++j) acc[r][j] = 0.f;

            #pragma unroll 2
            for (int d = 0; d < DIM; ++d) {
                float4 a0 = *reinterpret_cast<const float4*>(&xs[d][ty * 8]);
                float4 a1 = *reinterpret_cast<const float4*>(&xs[d][ty * 8 + 4]);
                float4 b0 = *reinterpret_cast<const float4*>(&u.ws[d][tx * 8]);
                float4 b1 = *reinterpret_cast<const float4*>(&u.ws[d][tx * 8 + 4]);
                float ar[8] = {a0.x, a0.y, a0.z, a0.w, a1.x, a1.y, a1.z, a1.w};
                float br[8] = {b0.x, b0.y, b0.z, b0.w, b1.x, b1.y, b1.z, b1.w};
                #pragma unroll
                for (int r = 0; r < 8; ++r)
                    #pragma unroll
                    for (int j = 0; j < 8; ++j)
                        acc[r][j] = fmaf(ar[r], br[j], acc[r][j]);
            }

            // epilogue: dist = w2 - 2*dot (x^2 per-row constant, argmin-invariant)
            #pragma unroll
            for (int j = 0; j < 8; ++j) {
                int kg = t8 * 128 + tx * 8 + j;
                float w2v = __ldg(&g_w2[kg]);
                #pragma unroll
                for (int r = 0; r < 8; ++r) {
                    float v = fmaf(-2.f, acc[r][j], w2v);
                    if (v < minv[r]) { minv[r] = v; mink[r] = kg; }
                }
            }
            __syncthreads();   // before overwriting ws / red
        }

        // --- cross-thread reduction (16 candidates per row)
        #pragma unroll
        for (int r = 0; r < 8; ++r) {
            int row = ty * 8 + r;
            u.red.rv[row][tx] = minv[r];
            u.red.ri[row][tx] = mink[r];
        }
        __syncthreads();

        if (tid < 64) {
            float bv = u.red.rv[tid][0];
            int   bi = u.red.ri[tid][0];
            #pragma unroll
            for (int t = 1; t < 16; ++t) {
                float v  = u.red.rv[tid][t];
                int   ii = u.red.ri[tid][t];
                if (v < bv || (v == bv && ii < bi)) { bv = v; bi = ii; }
            }
            g_idx[n0 + tid] = bi;
            atomicAdd(&g_counts[bi], 1);
            u.red.ri[tid][0] = bi;     // publish for dw scatter
        }
        __syncthreads();

        // --- dw scatter: dw[k][d] += x[n][d] (conflict-free smem reads)
        {
            int row   = tid & 63;
            int dbase = (tid >> 6) * 32;
            int kk = u.red.ri[row][0];
            float* dst = &g_dw[kk * DIM + dbase];
            #pragma unroll
            for (int i = 0; i < 32; ++i)
                atomicAdd(&dst[i], xs[dbase + i][row]);
        }
        __syncthreads();   // protect xs / red before next tile
    }
}

// ---------------------------------------------------------------------------
// Kernel C: codebook EMA update + perplexity (single block, 1024 threads)
// ---------------------------------------------------------------------------
__global__ void update_kernel(const float* __restrict__ ecs,
                              const float* __restrict__ emw,
                              float* __restrict__ out) {
    int k = threadIdx.x;
    __shared__ float sm[KCODE];

    float c   = (float)g_counts[k];
    float ncs = ecs[k] * 0.99f + 0.01f * c;
    out[NCS_OFF + k] = ncs;

    sm[k] = ncs; __syncthreads();
    for (int s = 512; s > 0; s >>= 1) {
        if (k < s) sm[k] += sm[k + s];
        __syncthreads();
    }
    float nsum = sm[0];
    __syncthreads();

    // perplexity
    float p = c * (1.f / (float)NVEC);
    sm[k] = p * logf(p + 1e-10f);
    __syncthreads();
    for (int s = 512; s > 0; s >>= 1) {
        if (k < s) sm[k] += sm[k + s];
        __syncthreads();
    }
    if (k == 0) out[PERP_OFF] = expf(-sm[0]);

    float normalized = (ncs + 1e-5f) / (nsum + 1024.f * 1e-5f) * nsum;
    float inv = 1.f / normalized;
    #pragma unroll
    for (int d = 0; d < DIM; ++d) {
        int i = k * DIM + d;
        float nw = emw[i] * 0.99f + 0.01f * g_dw[i];
        float e  = nw * inv;
        out[EMAW_OFF + i] = nw;
        out[EMBW_OFF + i] = e;
        g_embed[i] = e;            // aligned copy for float4 gathers in quant
    }
}

// ---------------------------------------------------------------------------
// Kernel D: quantize + loss. Each thread covers 4 consecutive d's per row so
// the codebook gather is one aligned float4 (from g_embed). grid = 1024.
// ---------------------------------------------------------------------------
__global__ void quant_kernel(const float* __restrict__ in,
                             float* __restrict__ out) {
    int blk = blockIdx.x;
    int b  = blk >> 6;
    int d0 = ((blk >> 2) & 15) * 4;
    int hc = blk & 3;
    int t  = threadIdx.x;

    const size_t pbase = (size_t)b * CHW + (size_t)d0 * HW;
    const int nbase = b * HW;

    float local = 0.f;
    #pragma unroll
    for (int it = 0; it < 4; ++it) {
        int hw = hc * 1024 + it * 256 + t;
        int kk = g_idx[nbase + hw];
        float4 q = *reinterpret_cast<const float4*>(&g_embed[kk * DIM + d0]);
        float qa[4] = {q.x, q.y, q.z, q.w};
        #pragma unroll
        for (int j = 0; j < 4; ++j) {
            size_t off = pbase + (size_t)j * HW + hw;
            float x = in[off];
            out[QUANT_OFF + off] = qa[j];   // x + (q - x) == q
            float diff = x - qa[j];
            local = fmaf(diff, diff, local);
        }
    }

    #pragma unroll
    for (int o = 16; o > 0; o >>= 1)
        local += __shfl_down_sync(0xffffffff, local, o);
    __shared__ float wsum[8];
    if ((t & 31) == 0) wsum[t >> 5] = local;
    __syncthreads();
    if (t == 0) {
        float s = 0.f;
        #pragma unroll
        for (int i = 0; i < 8; ++i) s += wsum[i];
        atomicAdd(&g_loss, s);
    }
}

// ---------------------------------------------------------------------------
// Kernel E: finalize loss
// ---------------------------------------------------------------------------
__global__ void loss_kernel(float* __restrict__ out) {
    out[LOSS_OFF] = 0.25f * g_loss * (1.f / (float)(NVEC * DIM));
}

extern "C" void kernel_launch(void* const* d_in, const int* in_sizes, int n_in,
                              void* d_out, int out_size) {
    const float* in  = (const float*)d_in[0];  // [16,64,64,64]
    const float* W   = (const float*)d_in[1];  // [1024,64]
    const float* ecs = (const float*)d_in[2];  // [1024]
    const float* emw = (const float*)d_in[3];  // [1024,64]
    float* out = (float*)d_out;

    prep_kernel<<<256, 256>>>(W);
    argmin_kernel<<<GRID_ARG, 128>>>(in);
    update_kernel<<<1, 1024>>>(ecs, emw, out);
    quant_kernel<<<1024, 256>>>(in, out);
    loss_kernel<<<1, 1>>>(out);
}